// round 7
// baseline (speedup 1.0000x reference)
#include <cuda_runtime.h>
#include <cuda_bf16.h>
#include <cstdint>

#define Bsz 4
#define Tt  4096
#define Dd  1024
#define Hh  8
#define DHh 128
#define Mrows (Bsz*Tt)     /* 16384 */
#define N3 (3*Dd)          /* 3072  */
#define LNEPS 1e-5f
#define NEGV (-1000000.0f)

// ---------------- scratch ----------------
__device__ __nv_bfloat16 g_xn[(size_t)Mrows*Dd];
__device__ __nv_bfloat16 g_Wcat[(size_t)Dd*N3];      // [k][n] bf16
__device__ __nv_bfloat16 g_q[(size_t)Mrows*Dd];
__device__ __nv_bfloat16 g_ek[(size_t)Mrows*Dd];
__device__ __nv_bfloat16 g_v[(size_t)Mrows*Dd];
__device__ float         g_colsum[Bsz*Dd];
__device__ float         g_attraw[Bsz*Hh*DHh*DHh];
__device__ __nv_bfloat16 g_att[Bsz*Hh*DHh*DHh];

// ---------------- PTX helpers ----------------
__device__ __forceinline__ uint32_t smem_u32(const void* p){
    return (uint32_t)__cvta_generic_to_shared(p);
}
__device__ __forceinline__ void cp16(void* s, const void* g){
    asm volatile("cp.async.cg.shared.global [%0], [%1], 16;\n" :: "r"(smem_u32(s)), "l"(g));
}
__device__ __forceinline__ void cp_commit(){ asm volatile("cp.async.commit_group;\n"); }
template<int N> __device__ __forceinline__ void cp_wait(){
    asm volatile("cp.async.wait_group %0;\n" :: "n"(N));
}
__device__ __forceinline__ void ldsm4(uint32_t* r, uint32_t a){
    asm volatile("ldmatrix.sync.aligned.m8n8.x4.shared.b16 {%0,%1,%2,%3}, [%4];\n"
        : "=r"(r[0]),"=r"(r[1]),"=r"(r[2]),"=r"(r[3]) : "r"(a));
}
__device__ __forceinline__ void ldsm4t(uint32_t* r, uint32_t a){
    asm volatile("ldmatrix.sync.aligned.m8n8.x4.trans.shared.b16 {%0,%1,%2,%3}, [%4];\n"
        : "=r"(r[0]),"=r"(r[1]),"=r"(r[2]),"=r"(r[3]) : "r"(a));
}
__device__ __forceinline__ void mma16816(float* c, const uint32_t* a, const uint32_t* b){
    asm volatile("mma.sync.aligned.m16n8k16.row.col.f32.bf16.bf16.f32 "
        "{%0,%1,%2,%3},{%4,%5,%6,%7},{%8,%9},{%0,%1,%2,%3};\n"
        : "+f"(c[0]),"+f"(c[1]),"+f"(c[2]),"+f"(c[3])
        : "r"(a[0]),"r"(a[1]),"r"(a[2]),"r"(a[3]),"r"(b[0]),"r"(b[1]));
}

// ---------------- 1. LayerNorm -> bf16 xn ----------------
__global__ __launch_bounds__(256) void ln_k(const float* __restrict__ x,
                                            const float* __restrict__ gamma,
                                            const float* __restrict__ beta){
    int row = blockIdx.x;
    int tid = threadIdx.x;
    const float* xr = x + (size_t)row*Dd;
    float4 v = *(const float4*)(xr + tid*4);
    float s  = v.x + v.y + v.z + v.w;
    float sq = v.x*v.x + v.y*v.y + v.z*v.z + v.w*v.w;
    #pragma unroll
    for (int o=16; o; o>>=1){
        s  += __shfl_xor_sync(0xffffffffu, s,  o);
        sq += __shfl_xor_sync(0xffffffffu, sq, o);
    }
    __shared__ float rs[8], rq[8];
    if ((tid&31)==0){ rs[tid>>5]=s; rq[tid>>5]=sq; }
    __syncthreads();
    float ts=0.f, tq=0.f;
    #pragma unroll
    for (int i=0;i<8;i++){ ts+=rs[i]; tq+=rq[i]; }
    float mu  = ts * (1.0f/Dd);
    float var = tq * (1.0f/Dd) - mu*mu;
    float rstd = rsqrtf(var + LNEPS);
    float4 g  = *(const float4*)(gamma + tid*4);
    float4 be = *(const float4*)(beta  + tid*4);
    float o0 = (v.x - mu)*rstd*g.x + be.x;
    float o1 = (v.y - mu)*rstd*g.y + be.y;
    float o2 = (v.z - mu)*rstd*g.z + be.z;
    float o3 = (v.w - mu)*rstd*g.w + be.w;
    __nv_bfloat16* dst = g_xn + (size_t)row*Dd + tid*4;
    *(__nv_bfloat162*)(dst)   = __nv_bfloat162(__float2bfloat16(o0), __float2bfloat16(o1));
    *(__nv_bfloat162*)(dst+2) = __nv_bfloat162(__float2bfloat16(o2), __float2bfloat16(o3));
}

// ---------------- 2. concat + bf16 weights [k][n] ----------------
__global__ void wcat_k(const float* __restrict__ Wq, const float* __restrict__ Wk,
                       const float* __restrict__ Wv){
    int idx = blockIdx.x*blockDim.x + threadIdx.x;
    if (idx >= Dd*N3) return;
    int k = idx / N3, j = idx % N3;
    float v = (j < Dd) ? Wq[k*Dd + j] : (j < 2*Dd) ? Wk[k*Dd + j - Dd] : Wv[k*Dd + j - 2*Dd];
    g_Wcat[idx] = __float2bfloat16(v);
}

// ---------------- 3. zero accumulators ----------------
__global__ void zero_k(){
    int idx = blockIdx.x*blockDim.x + threadIdx.x;
    if (idx < Bsz*Hh*DHh*DHh) g_attraw[idx] = 0.f;
    if (idx < Bsz*Dd) g_colsum[idx] = 0.f;
}

// ---------------- 4. fused QKV GEMM + activations (mma.sync, 3-stage) ----------------
// CTA tile 128x128, 4 warps (2x2), warp tile 64x64, K chunk 64, 3-stage pipeline.
#define AROW 72
#define BROW 136
#define NSTG 3
#define A_STG (128*AROW*2)         /* 18432 B */
#define B_STG (64*BROW*2)          /* 17408 B */
#define QKV_SMEM (NSTG*(A_STG+B_STG))   /* 107520 B */

__global__ __launch_bounds__(128) void qkv_gemm_fused(const float* __restrict__ bq,
                                                      const float* __restrict__ bk,
                                                      const float* __restrict__ bv,
                                                      const float* __restrict__ mask){
    extern __shared__ char sm[];
    __shared__ float red[128][2];
    __shared__ float sbias[128];

    const int tid = threadIdx.x, lane = tid&31, warp = tid>>5;
    const int wm = warp>>1, wn = warp&1;      // 2 x 2 warps, warp tile 64x64
    const int n0 = blockIdx.x*128, m0 = blockIdx.y*128;
    const int sec = n0 >> 10;                 // 0=q 1=k 2=v
    const int boff = n0 & (Dd-1);

    const __nv_bfloat16* Ag = g_xn + (size_t)m0*Dd;

    float acc[4][8][4];
    #pragma unroll
    for (int i=0;i<4;i++) for (int j=0;j<8;j++) for (int k=0;k<4;k++) acc[i][j][k]=0.f;

    auto As_ptr = [&](int s)->__nv_bfloat16 (*)[AROW]{
        return (__nv_bfloat16 (*)[AROW])(sm + s*(A_STG+B_STG));
    };
    auto Bs_ptr = [&](int s)->__nv_bfloat16 (*)[BROW]{
        return (__nv_bfloat16 (*)[BROW])(sm + s*(A_STG+B_STG) + A_STG);
    };

    auto load_chunk = [&](int s, int k0){
        __nv_bfloat16 (*A)[AROW] = As_ptr(s);
        __nv_bfloat16 (*B)[BROW] = Bs_ptr(s);
        #pragma unroll
        for (int i=0;i<8;i++){                    // A: 128x64 -> 1024 x 16B
            int c = tid + i*128;
            int r = c>>3, cc = c&7;
            cp16(&A[r][cc*8], Ag + (size_t)r*Dd + k0 + cc*8);
        }
        #pragma unroll
        for (int i=0;i<8;i++){                    // B: 64x128 -> 1024 x 16B
            int c = tid + i*128;
            int r = c>>4, cc = c&15;
            cp16(&B[r][cc*8], g_Wcat + (size_t)(k0+r)*N3 + n0 + cc*8);
        }
        cp_commit();
    };

    {   // stage bias for this 128-col tile
        const float* bias = (sec==0) ? bq : (sec==1) ? bk : bv;
        if (tid < 128) sbias[tid] = bias[boff + tid];
    }

    load_chunk(0, 0);
    load_chunk(1, 64);
    const int NT = Dd/64;
    int buf = 0;
    for (int kt=0; kt<NT; kt++){
        if (kt == NT-1) cp_wait<0>();
        else            cp_wait<1>();
        __syncthreads();
        if (kt+2 < NT) load_chunk((kt+2)%NSTG, (kt+2)*64);
        __nv_bfloat16 (*A)[AROW] = As_ptr(buf);
        __nv_bfloat16 (*B)[BROW] = Bs_ptr(buf);
        #pragma unroll
        for (int ks=0; ks<4; ks++){
            int kk = ks*16;
            uint32_t afr[4][4], bfr[4][4];
            #pragma unroll
            for (int mi=0;mi<4;mi++)
                ldsm4(afr[mi], smem_u32(&A[wm*64+mi*16+(lane&15)][kk+(lane>>4)*8]));
            #pragma unroll
            for (int bj=0;bj<4;bj++)
                ldsm4t(bfr[bj], smem_u32(&B[kk+(lane&15)][wn*64+bj*16+(lane>>4)*8]));
            #pragma unroll
            for (int mi=0;mi<4;mi++)
                #pragma unroll
                for (int ni=0;ni<8;ni++)
                    mma16816(acc[mi][ni], afr[mi], &bfr[ni>>1][(ni&1)*2]);
        }
        buf = (buf+1)%NSTG;
        __syncthreads();
    }

    // ---------------- fused epilogue ----------------
    const int r0 = lane>>2, c0 = (lane&3)*2;

    if (sec == 0){
        // q feature-softmax over 128 cols of this head (no max-sub; logits are O(1))
        float p0[4], p1[4];
        #pragma unroll
        for (int mi=0;mi<4;mi++){
            p0[mi]=0.f; p1[mi]=0.f;
            #pragma unroll
            for (int ni=0;ni<8;ni++){
                int cb = wn*64 + ni*8 + c0;
                acc[mi][ni][0] = __expf(acc[mi][ni][0] + sbias[cb]);
                acc[mi][ni][1] = __expf(acc[mi][ni][1] + sbias[cb+1]);
                acc[mi][ni][2] = __expf(acc[mi][ni][2] + sbias[cb]);
                acc[mi][ni][3] = __expf(acc[mi][ni][3] + sbias[cb+1]);
                p0[mi] += acc[mi][ni][0] + acc[mi][ni][1];
                p1[mi] += acc[mi][ni][2] + acc[mi][ni][3];
            }
            #pragma unroll
            for (int o=1;o<4;o<<=1){
                p0[mi] += __shfl_xor_sync(0xffffffffu, p0[mi], o);
                p1[mi] += __shfl_xor_sync(0xffffffffu, p1[mi], o);
            }
        }
        if ((lane&3)==0){
            #pragma unroll
            for (int mi=0;mi<4;mi++){
                red[wm*64+mi*16+r0][wn]   = p0[mi];
                red[wm*64+mi*16+r0+8][wn] = p1[mi];
            }
        }
        __syncthreads();
        #pragma unroll
        for (int mi=0;mi<4;mi++){
            int lr = wm*64+mi*16+r0;
            float inv0 = 1.0f/(red[lr][0]+red[lr][1]);
            float inv1 = 1.0f/(red[lr+8][0]+red[lr+8][1]);
            #pragma unroll
            for (int ni=0;ni<8;ni++){
                int col = boff + wn*64 + ni*8 + c0;
                size_t i0 = (size_t)(m0+lr)*Dd + col;
                size_t i1 = (size_t)(m0+lr+8)*Dd + col;
                *(__nv_bfloat162*)(g_q+i0) = __nv_bfloat162(__float2bfloat16(acc[mi][ni][0]*inv0),
                                                            __float2bfloat16(acc[mi][ni][1]*inv0));
                *(__nv_bfloat162*)(g_q+i1) = __nv_bfloat162(__float2bfloat16(acc[mi][ni][2]*inv1),
                                                            __float2bfloat16(acc[mi][ni][3]*inv1));
            }
        }
    } else if (sec == 1){
        // ek = exp(k + bias + mask) ; also accumulate colsum (fused)
        float cs[16];
        #pragma unroll
        for (int j=0;j<16;j++) cs[j] = 0.f;
        #pragma unroll
        for (int mi=0;mi<4;mi++){
            int row0 = m0 + wm*64 + mi*16 + r0;
            float a0 = (1.0f - __ldg(&mask[row0]))*NEGV;
            float a1 = (1.0f - __ldg(&mask[row0+8]))*NEGV;
            #pragma unroll
            for (int ni=0;ni<8;ni++){
                int cb = wn*64 + ni*8 + c0;
                int col = boff + cb;
                size_t i0 = (size_t)row0*Dd + col;
                size_t i1 = (size_t)(row0+8)*Dd + col;
                float e0 = __expf(acc[mi][ni][0] + sbias[cb]   + a0);
                float e1 = __expf(acc[mi][ni][1] + sbias[cb+1] + a0);
                float e2 = __expf(acc[mi][ni][2] + sbias[cb]   + a1);
                float e3 = __expf(acc[mi][ni][3] + sbias[cb+1] + a1);
                cs[2*ni]   += e0 + e2;
                cs[2*ni+1] += e1 + e3;
                *(__nv_bfloat162*)(g_ek+i0) = __nv_bfloat162(__float2bfloat16(e0), __float2bfloat16(e1));
                *(__nv_bfloat162*)(g_ek+i1) = __nv_bfloat162(__float2bfloat16(e2), __float2bfloat16(e3));
            }
        }
        // reduce across the 8 lane-groups (rows) of this warp
        #pragma unroll
        for (int o=4;o<32;o<<=1)
            #pragma unroll
            for (int j=0;j<16;j++) cs[j] += __shfl_xor_sync(0xffffffffu, cs[j], o);
        if (lane < 4){
            int b = m0 >> 12;                 // 4096 rows per batch
            #pragma unroll
            for (int ni=0;ni<8;ni++){
                int col = boff + wn*64 + ni*8 + (lane)*2;
                atomicAdd(&g_colsum[b*Dd + col],     cs[2*ni]);
                atomicAdd(&g_colsum[b*Dd + col + 1], cs[2*ni+1]);
            }
        }
    } else {
        #pragma unroll
        for (int mi=0;mi<4;mi++){
            int row0 = m0 + wm*64 + mi*16 + r0;
            float m0v = __ldg(&mask[row0]);
            float m1v = __ldg(&mask[row0+8]);
            #pragma unroll
            for (int ni=0;ni<8;ni++){
                int cb = wn*64 + ni*8 + c0;
                int col = boff + cb;
                size_t i0 = (size_t)row0*Dd + col;
                size_t i1 = (size_t)(row0+8)*Dd + col;
                *(__nv_bfloat162*)(g_v+i0) = __nv_bfloat162(
                    __float2bfloat16((acc[mi][ni][0] + sbias[cb])  *m0v),
                    __float2bfloat16((acc[mi][ni][1] + sbias[cb+1])*m0v));
                *(__nv_bfloat162*)(g_v+i1) = __nv_bfloat162(
                    __float2bfloat16((acc[mi][ni][2] + sbias[cb])  *m1v),
                    __float2bfloat16((acc[mi][ni][3] + sbias[cb+1])*m1v));
            }
        }
    }
}

// ---------------- 6. att = ek^T v per (b,h), split-K over time ----------------
#define ATT_SPLIT 16
#define ATT_CHUNK (Tt/ATT_SPLIT)   /* 256 */
__global__ __launch_bounds__(256) void att_gemm(){
    __shared__ __nv_bfloat16 Ae[2][32][136];
    __shared__ __nv_bfloat16 Vs[2][32][136];
    const int tid = threadIdx.x, lane = tid&31, warp = tid>>5;
    const int wm = warp>>2, wn = warp&3;
    int chunk = blockIdx.x, bh = blockIdx.y;
    int b = bh>>3, h = bh&7;
    const __nv_bfloat16* Ep = g_ek + (size_t)(b*Tt + chunk*ATT_CHUNK)*Dd + h*DHh;
    const __nv_bfloat16* Vp = g_v  + (size_t)(b*Tt + chunk*ATT_CHUNK)*Dd + h*DHh;
    float acc[4][4][4];
    #pragma unroll
    for (int i=0;i<4;i++) for (int j=0;j<4;j++) for (int k=0;k<4;k++) acc[i][j][k]=0.f;

    auto load_tiles = [&](int buf, int k0){
        #pragma unroll
        for (int i=0;i<2;i++){
            int c = tid + i*256;
            int r = c>>4, cc = c&15;
            cp16(&Ae[buf][r][cc*8], Ep + (size_t)(k0+r)*Dd + cc*8);
            cp16(&Vs[buf][r][cc*8], Vp + (size_t)(k0+r)*Dd + cc*8);
        }
    };
    load_tiles(0,0); cp_commit();
    const int NT = ATT_CHUNK/32;
    for (int kt=0; kt<NT; kt++){
        int buf = kt&1;
        if (kt+1 < NT){ load_tiles(buf^1, (kt+1)*32); cp_commit(); cp_wait<1>(); }
        else          { cp_wait<0>(); }
        __syncthreads();
        #pragma unroll
        for (int ks=0; ks<2; ks++){
            int kk = ks*16;
            uint32_t afr[4][4], bfr[2][4], raw[4];
            #pragma unroll
            for (int mi=0;mi<4;mi++){
                ldsm4t(raw, smem_u32(&Ae[buf][kk+(lane&15)][wm*64+mi*16+(lane>>4)*8]));
                afr[mi][0]=raw[0]; afr[mi][1]=raw[2]; afr[mi][2]=raw[1]; afr[mi][3]=raw[3];
            }
            #pragma unroll
            for (int bj=0;bj<2;bj++)
                ldsm4t(bfr[bj], smem_u32(&Vs[buf][kk+(lane&15)][wn*32+bj*16+(lane>>4)*8]));
            #pragma unroll
            for (int mi=0;mi<4;mi++)
                #pragma unroll
                for (int ni=0;ni<4;ni++)
                    mma16816(acc[mi][ni], afr[mi], &bfr[ni>>1][(ni&1)*2]);
        }
        __syncthreads();
    }
    int r0 = lane>>2, c0 = (lane&3)*2;
    #pragma unroll
    for (int mi=0;mi<4;mi++)
        #pragma unroll
        for (int ni=0;ni<4;ni++){
            int row = wm*64 + mi*16 + r0;
            int col = wn*32 + ni*8 + c0;
            float* base = g_attraw + (size_t)bh*DHh*DHh;
            atomicAdd(&base[(size_t)row*DHh + col],     acc[mi][ni][0]);
            atomicAdd(&base[(size_t)row*DHh + col + 1], acc[mi][ni][1]);
            atomicAdd(&base[(size_t)(row+8)*DHh + col],     acc[mi][ni][2]);
            atomicAdd(&base[(size_t)(row+8)*DHh + col + 1], acc[mi][ni][3]);
        }
}

// ---------------- 7. att scale by 1/colsum -> bf16 ----------------
__global__ void att_scale(){
    int idx = blockIdx.x*blockDim.x + threadIdx.x;
    if (idx >= Bsz*Hh*DHh*DHh) return;
    int d  = (idx>>7) & 127;
    int bh = idx>>14;
    int b = bh>>3, h = bh&7;
    g_att[idx] = __float2bfloat16(g_attraw[idx] / g_colsum[b*Dd + h*DHh + d]);
}

// ---------------- 8. y = q * att, out = x + y ----------------
__global__ __launch_bounds__(256) void y_gemm(const float* __restrict__ x, float* __restrict__ out){
    __shared__ __nv_bfloat16 As[2][128][40];
    __shared__ __nv_bfloat16 Bsm[2][32][136];
    const int tid = threadIdx.x, lane = tid&31, warp = tid>>5;
    const int wm = warp>>2, wn = warp&3;
    int tt = blockIdx.x, bh = blockIdx.y;
    int b = bh>>3, h = bh&7;
    const __nv_bfloat16* Ap = g_q   + (size_t)(b*Tt + tt*128)*Dd + h*DHh;
    const __nv_bfloat16* Bp = g_att + (size_t)bh*DHh*DHh;
    float acc[4][4][4];
    #pragma unroll
    for (int i=0;i<4;i++) for (int j=0;j<4;j++) for (int k=0;k<4;k++) acc[i][j][k]=0.f;

    auto load_tiles = [&](int buf, int k0){
        #pragma unroll
        for (int i=0;i<2;i++){
            int c = tid + i*256;
            int r = c>>2, cc = c&3;
            cp16(&As[buf][r][cc*8], Ap + (size_t)r*Dd + k0 + cc*8);
        }
        #pragma unroll
        for (int i=0;i<2;i++){
            int c = tid + i*256;
            int r = c>>4, cc = c&15;
            cp16(&Bsm[buf][r][cc*8], Bp + (size_t)(k0+r)*DHh + cc*8);
        }
    };
    load_tiles(0,0); cp_commit();
    const int NT = DHh/32;
    for (int kt=0; kt<NT; kt++){
        int buf = kt&1;
        if (kt+1 < NT){ load_tiles(buf^1, (kt+1)*32); cp_commit(); cp_wait<1>(); }
        else          { cp_wait<0>(); }
        __syncthreads();
        #pragma unroll
        for (int ks=0; ks<2; ks++){
            int kk = ks*16;
            uint32_t afr[4][4], bfr[2][4];
            #pragma unroll
            for (int mi=0;mi<4;mi++)
                ldsm4(afr[mi], smem_u32(&As[buf][wm*64+mi*16+(lane&15)][kk+(lane>>4)*8]));
            #pragma unroll
            for (int bj=0;bj<2;bj++)
                ldsm4t(bfr[bj], smem_u32(&Bsm[buf][kk+(lane&15)][wn*32+bj*16+(lane>>4)*8]));
            #pragma unroll
            for (int mi=0;mi<4;mi++)
                #pragma unroll
                for (int ni=0;ni<4;ni++)
                    mma16816(acc[mi][ni], afr[mi], &bfr[ni>>1][(ni&1)*2]);
        }
        __syncthreads();
    }
    int r0 = lane>>2, c0 = (lane&3)*2;
    #pragma unroll
    for (int mi=0;mi<4;mi++)
        #pragma unroll
        for (int ni=0;ni<4;ni++){
            int trow = tt*128 + wm*64 + mi*16 + r0;
            int col  = wn*32 + ni*8 + c0;
            size_t i0 = (size_t)(b*Tt + trow)*Dd + h*DHh + col;
            size_t i1 = (size_t)(b*Tt + trow + 8)*Dd + h*DHh + col;
            out[i0]   = x[i0]   + acc[mi][ni][0];
            out[i0+1] = x[i0+1] + acc[mi][ni][1];
            out[i1]   = x[i1]   + acc[mi][ni][2];
            out[i1+1] = x[i1+1] + acc[mi][ni][3];
        }
}

// ---------------- launch ----------------
extern "C" void kernel_launch(void* const* d_in, const int* in_sizes, int n_in,
                              void* d_out, int out_size){
    const float* x     = (const float*)d_in[0];
    const float* mask  = (const float*)d_in[1];
    const float* Wq    = (const float*)d_in[2];
    const float* bq    = (const float*)d_in[3];
    const float* Wk    = (const float*)d_in[4];
    const float* bk    = (const float*)d_in[5];
    const float* Wv    = (const float*)d_in[6];
    const float* bv    = (const float*)d_in[7];
    const float* gamma = (const float*)d_in[8];
    const float* beta  = (const float*)d_in[9];
    float* out = (float*)d_out;

    static bool cfg = false;
    if (!cfg){
        cudaFuncSetAttribute(qkv_gemm_fused, cudaFuncAttributeMaxDynamicSharedMemorySize, QKV_SMEM);
        cfg = true;
    }

    ln_k<<<Mrows, 256>>>(x, gamma, beta);
    wcat_k<<<(Dd*N3 + 255)/256, 256>>>(Wq, Wk, Wv);
    zero_k<<<(Bsz*Hh*DHh*DHh + 255)/256, 256>>>();
    qkv_gemm_fused<<<dim3(N3/128, Mrows/128), 128, QKV_SMEM>>>(bq, bk, bv, mask);
    att_gemm<<<dim3(ATT_SPLIT, Bsz*Hh), 256>>>();
    att_scale<<<(Bsz*Hh*DHh*DHh)/256, 256>>>();
    y_gemm<<<dim3(Tt/128, Bsz*Hh), 256>>>(x, out);
}

// round 14
// speedup vs baseline: 1.0599x; 1.0599x over previous
#include <cuda_runtime.h>
#include <cuda_bf16.h>
#include <cstdint>

#define Bsz 4
#define Tt  4096
#define Dd  1024
#define Hh  8
#define DHh 128
#define Mrows (Bsz*Tt)     /* 16384 */
#define N3 (3*Dd)          /* 3072  */
#define LNEPS 1e-5f
#define NEGV (-1000000.0f)

// ---------------- scratch ----------------
__device__ __nv_bfloat16 g_xn[(size_t)Mrows*Dd];
__device__ __nv_bfloat16 g_Wcat[(size_t)Dd*N3];      // [k][n] bf16
__device__ __nv_bfloat16 g_q[(size_t)Mrows*Dd];
__device__ __nv_bfloat16 g_ek[(size_t)Mrows*Dd];
__device__ __nv_bfloat16 g_v[(size_t)Mrows*Dd];
__device__ float         g_colsum[Bsz*Dd];
__device__ float         g_attraw[Bsz*Hh*DHh*DHh];
__device__ __nv_bfloat16 g_att[Bsz*Hh*DHh*DHh];

// ---------------- PTX helpers ----------------
__device__ __forceinline__ uint32_t smem_u32(const void* p){
    return (uint32_t)__cvta_generic_to_shared(p);
}
__device__ __forceinline__ void cp16(void* s, const void* g){
    asm volatile("cp.async.cg.shared.global [%0], [%1], 16;\n" :: "r"(smem_u32(s)), "l"(g));
}
__device__ __forceinline__ void cp_commit(){ asm volatile("cp.async.commit_group;\n"); }
template<int N> __device__ __forceinline__ void cp_wait(){
    asm volatile("cp.async.wait_group %0;\n" :: "n"(N));
}
__device__ __forceinline__ void ldsm4(uint32_t* r, uint32_t a){
    asm volatile("ldmatrix.sync.aligned.m8n8.x4.shared.b16 {%0,%1,%2,%3}, [%4];\n"
        : "=r"(r[0]),"=r"(r[1]),"=r"(r[2]),"=r"(r[3]) : "r"(a));
}
__device__ __forceinline__ void ldsm4t(uint32_t* r, uint32_t a){
    asm volatile("ldmatrix.sync.aligned.m8n8.x4.trans.shared.b16 {%0,%1,%2,%3}, [%4];\n"
        : "=r"(r[0]),"=r"(r[1]),"=r"(r[2]),"=r"(r[3]) : "r"(a));
}
__device__ __forceinline__ void mma16816(float* c, const uint32_t* a, const uint32_t* b){
    asm volatile("mma.sync.aligned.m16n8k16.row.col.f32.bf16.bf16.f32 "
        "{%0,%1,%2,%3},{%4,%5,%6,%7},{%8,%9},{%0,%1,%2,%3};\n"
        : "+f"(c[0]),"+f"(c[1]),"+f"(c[2]),"+f"(c[3])
        : "r"(a[0]),"r"(a[1]),"r"(a[2]),"r"(a[3]),"r"(b[0]),"r"(b[1]));
}

// ---------------- 1. LayerNorm -> bf16 xn ----------------
__global__ __launch_bounds__(256) void ln_k(const float* __restrict__ x,
                                            const float* __restrict__ gamma,
                                            const float* __restrict__ beta){
    int row = blockIdx.x;
    int tid = threadIdx.x;
    const float* xr = x + (size_t)row*Dd;
    float4 v = *(const float4*)(xr + tid*4);
    float s  = v.x + v.y + v.z + v.w;
    float sq = v.x*v.x + v.y*v.y + v.z*v.z + v.w*v.w;
    #pragma unroll
    for (int o=16; o; o>>=1){
        s  += __shfl_xor_sync(0xffffffffu, s,  o);
        sq += __shfl_xor_sync(0xffffffffu, sq, o);
    }
    __shared__ float rs[8], rq[8];
    if ((tid&31)==0){ rs[tid>>5]=s; rq[tid>>5]=sq; }
    __syncthreads();
    float ts=0.f, tq=0.f;
    #pragma unroll
    for (int i=0;i<8;i++){ ts+=rs[i]; tq+=rq[i]; }
    float mu  = ts * (1.0f/Dd);
    float var = tq * (1.0f/Dd) - mu*mu;
    float rstd = rsqrtf(var + LNEPS);
    float4 g  = *(const float4*)(gamma + tid*4);
    float4 be = *(const float4*)(beta  + tid*4);
    float o0 = (v.x - mu)*rstd*g.x + be.x;
    float o1 = (v.y - mu)*rstd*g.y + be.y;
    float o2 = (v.z - mu)*rstd*g.z + be.z;
    float o3 = (v.w - mu)*rstd*g.w + be.w;
    __nv_bfloat16* dst = g_xn + (size_t)row*Dd + tid*4;
    *(__nv_bfloat162*)(dst)   = __nv_bfloat162(__float2bfloat16(o0), __float2bfloat16(o1));
    *(__nv_bfloat162*)(dst+2) = __nv_bfloat162(__float2bfloat16(o2), __float2bfloat16(o3));
}

// ---------------- 2. concat + bf16 weights [k][n] ----------------
__global__ void wcat_k(const float* __restrict__ Wq, const float* __restrict__ Wk,
                       const float* __restrict__ Wv){
    int idx = blockIdx.x*blockDim.x + threadIdx.x;
    if (idx >= Dd*N3) return;
    int k = idx / N3, j = idx % N3;
    float v = (j < Dd) ? Wq[k*Dd + j] : (j < 2*Dd) ? Wk[k*Dd + j - Dd] : Wv[k*Dd + j - 2*Dd];
    g_Wcat[idx] = __float2bfloat16(v);
}

// ---------------- 3. zero accumulators ----------------
__global__ void zero_k(){
    int idx = blockIdx.x*blockDim.x + threadIdx.x;
    if (idx < Bsz*Hh*DHh*DHh) g_attraw[idx] = 0.f;
    if (idx < Bsz*Dd) g_colsum[idx] = 0.f;
}

// ---------------- 4. fused QKV GEMM + activations (mma.sync, 2-stage, 1 sync/chunk) ----------------
// CTA tile 128x128, 4 warps (2x2), warp tile 64x64, K chunk 64, double-buffered.
// Pipeline invariant: next chunk is issued AFTER the sync, so at most one group
// is pending at the top of an iteration -> must use cp_wait<0> (wait ALL).
#define AROW 72
#define BROW 136
#define QKV_SMEM (2*(128*AROW + 64*BROW)*2)   /* 71680 B */

__global__ __launch_bounds__(128) void qkv_gemm_fused(const float* __restrict__ bq,
                                                      const float* __restrict__ bk,
                                                      const float* __restrict__ bv,
                                                      const float* __restrict__ mask){
    extern __shared__ char sm[];
    __nv_bfloat16 (*As)[128][AROW] = (__nv_bfloat16 (*)[128][AROW])sm;
    __nv_bfloat16 (*Bs)[64][BROW]  = (__nv_bfloat16 (*)[64][BROW])(sm + 2*128*AROW*2);
    __shared__ float red[128][2];
    __shared__ float sbias[128];

    const int tid = threadIdx.x, lane = tid&31, warp = tid>>5;
    const int wm = warp>>1, wn = warp&1;      // 2 x 2 warps, warp tile 64x64
    const int n0 = blockIdx.x*128, m0 = blockIdx.y*128;
    const int sec = n0 >> 10;                 // 0=q 1=k 2=v
    const int boff = n0 & (Dd-1);

    const __nv_bfloat16* Ag = g_xn + (size_t)m0*Dd;

    float acc[4][8][4];
    #pragma unroll
    for (int i=0;i<4;i++) for (int j=0;j<8;j++) for (int k=0;k<4;k++) acc[i][j][k]=0.f;

    auto load_chunk = [&](int buf, int k0){
        #pragma unroll
        for (int i=0;i<8;i++){                    // A: 128x64 -> 1024 x 16B
            int c = tid + i*128;
            int r = c>>3, cc = c&7;
            cp16(&As[buf][r][cc*8], Ag + (size_t)r*Dd + k0 + cc*8);
        }
        #pragma unroll
        for (int i=0;i<8;i++){                    // B: 64x128 -> 1024 x 16B
            int c = tid + i*128;
            int r = c>>4, cc = c&15;
            cp16(&Bs[buf][r][cc*8], g_Wcat + (size_t)(k0+r)*N3 + n0 + cc*8);
        }
        cp_commit();
    };

    {   // stage bias for this 128-col tile
        const float* bias = (sec==0) ? bq : (sec==1) ? bk : bv;
        if (tid < 128) sbias[tid] = bias[boff + tid];
    }

    load_chunk(0, 0);
    const int NT = Dd/64;
    for (int kt=0; kt<NT; kt++){
        int buf = kt&1;
        cp_wait<0>();       // this chunk's data landed (only its group can be pending)
        __syncthreads();    // ...and everyone finished reading buf^1 -> safe to refill
        if (kt+1 < NT) load_chunk(buf^1, (kt+1)*64);
        #pragma unroll
        for (int ks=0; ks<4; ks++){
            int kk = ks*16;
            uint32_t afr[4][4], bfr[4][4];
            #pragma unroll
            for (int mi=0;mi<4;mi++)
                ldsm4(afr[mi], smem_u32(&As[buf][wm*64+mi*16+(lane&15)][kk+(lane>>4)*8]));
            #pragma unroll
            for (int bj=0;bj<4;bj++)
                ldsm4t(bfr[bj], smem_u32(&Bs[buf][kk+(lane&15)][wn*64+bj*16+(lane>>4)*8]));
            #pragma unroll
            for (int mi=0;mi<4;mi++)
                #pragma unroll
                for (int ni=0;ni<8;ni++)
                    mma16816(acc[mi][ni], afr[mi], &bfr[ni>>1][(ni&1)*2]);
        }
    }

    // ---------------- fused epilogue ----------------
    const int r0 = lane>>2, c0 = (lane&3)*2;

    if (sec == 0){
        // q feature-softmax over 128 cols of this head (no max-sub; logits are O(1))
        float p0[4], p1[4];
        #pragma unroll
        for (int mi=0;mi<4;mi++){
            p0[mi]=0.f; p1[mi]=0.f;
            #pragma unroll
            for (int ni=0;ni<8;ni++){
                int cb = wn*64 + ni*8 + c0;
                acc[mi][ni][0] = __expf(acc[mi][ni][0] + sbias[cb]);
                acc[mi][ni][1] = __expf(acc[mi][ni][1] + sbias[cb+1]);
                acc[mi][ni][2] = __expf(acc[mi][ni][2] + sbias[cb]);
                acc[mi][ni][3] = __expf(acc[mi][ni][3] + sbias[cb+1]);
                p0[mi] += acc[mi][ni][0] + acc[mi][ni][1];
                p1[mi] += acc[mi][ni][2] + acc[mi][ni][3];
            }
            #pragma unroll
            for (int o=1;o<4;o<<=1){
                p0[mi] += __shfl_xor_sync(0xffffffffu, p0[mi], o);
                p1[mi] += __shfl_xor_sync(0xffffffffu, p1[mi], o);
            }
        }
        __syncthreads();
        if ((lane&3)==0){
            #pragma unroll
            for (int mi=0;mi<4;mi++){
                red[wm*64+mi*16+r0][wn]   = p0[mi];
                red[wm*64+mi*16+r0+8][wn] = p1[mi];
            }
        }
        __syncthreads();
        #pragma unroll
        for (int mi=0;mi<4;mi++){
            int lr = wm*64+mi*16+r0;
            float inv0 = 1.0f/(red[lr][0]+red[lr][1]);
            float inv1 = 1.0f/(red[lr+8][0]+red[lr+8][1]);
            #pragma unroll
            for (int ni=0;ni<8;ni++){
                int col = boff + wn*64 + ni*8 + c0;
                size_t i0 = (size_t)(m0+lr)*Dd + col;
                size_t i1 = (size_t)(m0+lr+8)*Dd + col;
                *(__nv_bfloat162*)(g_q+i0) = __nv_bfloat162(__float2bfloat16(acc[mi][ni][0]*inv0),
                                                            __float2bfloat16(acc[mi][ni][1]*inv0));
                *(__nv_bfloat162*)(g_q+i1) = __nv_bfloat162(__float2bfloat16(acc[mi][ni][2]*inv1),
                                                            __float2bfloat16(acc[mi][ni][3]*inv1));
            }
        }
    } else if (sec == 1){
        // ek = exp(k + bias + mask) ; also accumulate colsum (fused)
        float cs[16];
        #pragma unroll
        for (int j=0;j<16;j++) cs[j] = 0.f;
        #pragma unroll
        for (int mi=0;mi<4;mi++){
            int row0 = m0 + wm*64 + mi*16 + r0;
            float a0 = (1.0f - __ldg(&mask[row0]))*NEGV;
            float a1 = (1.0f - __ldg(&mask[row0+8]))*NEGV;
            #pragma unroll
            for (int ni=0;ni<8;ni++){
                int cb = wn*64 + ni*8 + c0;
                int col = boff + cb;
                size_t i0 = (size_t)row0*Dd + col;
                size_t i1 = (size_t)(row0+8)*Dd + col;
                float e0 = __expf(acc[mi][ni][0] + sbias[cb]   + a0);
                float e1 = __expf(acc[mi][ni][1] + sbias[cb+1] + a0);
                float e2 = __expf(acc[mi][ni][2] + sbias[cb]   + a1);
                float e3 = __expf(acc[mi][ni][3] + sbias[cb+1] + a1);
                cs[2*ni]   += e0 + e2;
                cs[2*ni+1] += e1 + e3;
                *(__nv_bfloat162*)(g_ek+i0) = __nv_bfloat162(__float2bfloat16(e0), __float2bfloat16(e1));
                *(__nv_bfloat162*)(g_ek+i1) = __nv_bfloat162(__float2bfloat16(e2), __float2bfloat16(e3));
            }
        }
        // reduce across the 8 lane-groups (rows) of this warp
        #pragma unroll
        for (int o=4;o<32;o<<=1)
            #pragma unroll
            for (int j=0;j<16;j++) cs[j] += __shfl_xor_sync(0xffffffffu, cs[j], o);
        if (lane < 4){
            int b = m0 >> 12;                 // 4096 rows per batch
            #pragma unroll
            for (int ni=0;ni<8;ni++){
                int col = boff + wn*64 + ni*8 + (lane)*2;
                atomicAdd(&g_colsum[b*Dd + col],     cs[2*ni]);
                atomicAdd(&g_colsum[b*Dd + col + 1], cs[2*ni+1]);
            }
        }
    } else {
        #pragma unroll
        for (int mi=0;mi<4;mi++){
            int row0 = m0 + wm*64 + mi*16 + r0;
            float m0v = __ldg(&mask[row0]);
            float m1v = __ldg(&mask[row0+8]);
            #pragma unroll
            for (int ni=0;ni<8;ni++){
                int cb = wn*64 + ni*8 + c0;
                int col = boff + cb;
                size_t i0 = (size_t)row0*Dd + col;
                size_t i1 = (size_t)(row0+8)*Dd + col;
                *(__nv_bfloat162*)(g_v+i0) = __nv_bfloat162(
                    __float2bfloat16((acc[mi][ni][0] + sbias[cb])  *m0v),
                    __float2bfloat16((acc[mi][ni][1] + sbias[cb+1])*m0v));
                *(__nv_bfloat162*)(g_v+i1) = __nv_bfloat162(
                    __float2bfloat16((acc[mi][ni][2] + sbias[cb])  *m1v),
                    __float2bfloat16((acc[mi][ni][3] + sbias[cb+1])*m1v));
            }
        }
    }
}

// ---------------- 6. att = ek^T v per (b,h), split-K over time ----------------
#define ATT_SPLIT 16
#define ATT_CHUNK (Tt/ATT_SPLIT)   /* 256 */
__global__ __launch_bounds__(256) void att_gemm(){
    __shared__ __nv_bfloat16 Ae[2][32][136];
    __shared__ __nv_bfloat16 Vs[2][32][136];
    const int tid = threadIdx.x, lane = tid&31, warp = tid>>5;
    const int wm = warp>>2, wn = warp&3;
    int chunk = blockIdx.x, bh = blockIdx.y;
    int b = bh>>3, h = bh&7;
    const __nv_bfloat16* Ep = g_ek + (size_t)(b*Tt + chunk*ATT_CHUNK)*Dd + h*DHh;
    const __nv_bfloat16* Vp = g_v  + (size_t)(b*Tt + chunk*ATT_CHUNK)*Dd + h*DHh;
    float acc[4][4][4];
    #pragma unroll
    for (int i=0;i<4;i++) for (int j=0;j<4;j++) for (int k=0;k<4;k++) acc[i][j][k]=0.f;

    auto load_tiles = [&](int buf, int k0){
        #pragma unroll
        for (int i=0;i<2;i++){
            int c = tid + i*256;
            int r = c>>4, cc = c&15;
            cp16(&Ae[buf][r][cc*8], Ep + (size_t)(k0+r)*Dd + cc*8);
            cp16(&Vs[buf][r][cc*8], Vp + (size_t)(k0+r)*Dd + cc*8);
        }
        cp_commit();
    };
    load_tiles(0,0);
    const int NT = ATT_CHUNK/32;
    for (int kt=0; kt<NT; kt++){
        int buf = kt&1;
        cp_wait<0>();
        __syncthreads();
        if (kt+1 < NT) load_tiles(buf^1, (kt+1)*32);
        #pragma unroll
        for (int ks=0; ks<2; ks++){
            int kk = ks*16;
            uint32_t afr[4][4], bfr[2][4], raw[4];
            #pragma unroll
            for (int mi=0;mi<4;mi++){
                ldsm4t(raw, smem_u32(&Ae[buf][kk+(lane&15)][wm*64+mi*16+(lane>>4)*8]));
                afr[mi][0]=raw[0]; afr[mi][1]=raw[2]; afr[mi][2]=raw[1]; afr[mi][3]=raw[3];
            }
            #pragma unroll
            for (int bj=0;bj<2;bj++)
                ldsm4t(bfr[bj], smem_u32(&Vs[buf][kk+(lane&15)][wn*32+bj*16+(lane>>4)*8]));
            #pragma unroll
            for (int mi=0;mi<4;mi++)
                #pragma unroll
                for (int ni=0;ni<4;ni++)
                    mma16816(acc[mi][ni], afr[mi], &bfr[ni>>1][(ni&1)*2]);
        }
    }
    int r0 = lane>>2, c0 = (lane&3)*2;
    #pragma unroll
    for (int mi=0;mi<4;mi++)
        #pragma unroll
        for (int ni=0;ni<4;ni++){
            int row = wm*64 + mi*16 + r0;
            int col = wn*32 + ni*8 + c0;
            float* base = g_attraw + (size_t)bh*DHh*DHh;
            atomicAdd(&base[(size_t)row*DHh + col],     acc[mi][ni][0]);
            atomicAdd(&base[(size_t)row*DHh + col + 1], acc[mi][ni][1]);
            atomicAdd(&base[(size_t)(row+8)*DHh + col],     acc[mi][ni][2]);
            atomicAdd(&base[(size_t)(row+8)*DHh + col + 1], acc[mi][ni][3]);
        }
}

// ---------------- 7. att scale by 1/colsum -> bf16 ----------------
__global__ void att_scale(){
    int idx = blockIdx.x*blockDim.x + threadIdx.x;
    if (idx >= Bsz*Hh*DHh*DHh) return;
    int d  = (idx>>7) & 127;
    int bh = idx>>14;
    int b = bh>>3, h = bh&7;
    g_att[idx] = __float2bfloat16(g_attraw[idx] / g_colsum[b*Dd + h*DHh + d]);
}

// ---------------- 8. y = q * att, out = x + y ----------------
__global__ __launch_bounds__(256) void y_gemm(const float* __restrict__ x, float* __restrict__ out){
    __shared__ __nv_bfloat16 As[2][128][40];
    __shared__ __nv_bfloat16 Bsm[2][32][136];
    const int tid = threadIdx.x, lane = tid&31, warp = tid>>5;
    const int wm = warp>>2, wn = warp&3;
    int tt = blockIdx.x, bh = blockIdx.y;
    int b = bh>>3, h = bh&7;
    const __nv_bfloat16* Ap = g_q   + (size_t)(b*Tt + tt*128)*Dd + h*DHh;
    const __nv_bfloat16* Bp = g_att + (size_t)bh*DHh*DHh;
    float acc[4][4][4];
    #pragma unroll
    for (int i=0;i<4;i++) for (int j=0;j<4;j++) for (int k=0;k<4;k++) acc[i][j][k]=0.f;

    auto load_tiles = [&](int buf, int k0){
        #pragma unroll
        for (int i=0;i<2;i++){
            int c = tid + i*256;
            int r = c>>2, cc = c&3;
            cp16(&As[buf][r][cc*8], Ap + (size_t)r*Dd + k0 + cc*8);
        }
        #pragma unroll
        for (int i=0;i<2;i++){
            int c = tid + i*256;
            int r = c>>4, cc = c&15;
            cp16(&Bsm[buf][r][cc*8], Bp + (size_t)(k0+r)*DHh + cc*8);
        }
        cp_commit();
    };
    load_tiles(0,0);
    const int NT = DHh/32;
    for (int kt=0; kt<NT; kt++){
        int buf = kt&1;
        cp_wait<0>();
        __syncthreads();
        if (kt+1 < NT) load_tiles(buf^1, (kt+1)*32);
        #pragma unroll
        for (int ks=0; ks<2; ks++){
            int kk = ks*16;
            uint32_t afr[4][4], bfr[2][4];
            #pragma unroll
            for (int mi=0;mi<4;mi++)
                ldsm4(afr[mi], smem_u32(&As[buf][wm*64+mi*16+(lane&15)][kk+(lane>>4)*8]));
            #pragma unroll
            for (int bj=0;bj<2;bj++)
                ldsm4t(bfr[bj], smem_u32(&Bsm[buf][kk+(lane&15)][wn*32+bj*16+(lane>>4)*8]));
            #pragma unroll
            for (int mi=0;mi<4;mi++)
                #pragma unroll
                for (int ni=0;ni<4;ni++)
                    mma16816(acc[mi][ni], afr[mi], &bfr[ni>>1][(ni&1)*2]);
        }
    }
    int r0 = lane>>2, c0 = (lane&3)*2;
    #pragma unroll
    for (int mi=0;mi<4;mi++)
        #pragma unroll
        for (int ni=0;ni<4;ni++){
            int trow = tt*128 + wm*64 + mi*16 + r0;
            int col  = wn*32 + ni*8 + c0;
            size_t i0 = (size_t)(b*Tt + trow)*Dd + h*DHh + col;
            size_t i1 = (size_t)(b*Tt + trow + 8)*Dd + h*DHh + col;
            out[i0]   = x[i0]   + acc[mi][ni][0];
            out[i0+1] = x[i0+1] + acc[mi][ni][1];
            out[i1]   = x[i1]   + acc[mi][ni][2];
            out[i1+1] = x[i1+1] + acc[mi][ni][3];
        }
}

// ---------------- launch ----------------
extern "C" void kernel_launch(void* const* d_in, const int* in_sizes, int n_in,
                              void* d_out, int out_size){
    const float* x     = (const float*)d_in[0];
    const float* mask  = (const float*)d_in[1];
    const float* Wq    = (const float*)d_in[2];
    const float* bq    = (const float*)d_in[3];
    const float* Wk    = (const float*)d_in[4];
    const float* bk    = (const float*)d_in[5];
    const float* Wv    = (const float*)d_in[6];
    const float* bv    = (const float*)d_in[7];
    const float* gamma = (const float*)d_in[8];
    const float* beta  = (const float*)d_in[9];
    float* out = (float*)d_out;

    static bool cfg = false;
    if (!cfg){
        cudaFuncSetAttribute(qkv_gemm_fused, cudaFuncAttributeMaxDynamicSharedMemorySize, QKV_SMEM);
        cfg = true;
    }

    ln_k<<<Mrows, 256>>>(x, gamma, beta);
    wcat_k<<<(Dd*N3 + 255)/256, 256>>>(Wq, Wk, Wv);
    zero_k<<<(Bsz*Hh*DHh*DHh + 255)/256, 256>>>();
    qkv_gemm_fused<<<dim3(N3/128, Mrows/128), 128, QKV_SMEM>>>(bq, bk, bv, mask);
    att_gemm<<<dim3(ATT_SPLIT, Bsz*Hh), 256>>>();
    att_scale<<<(Bsz*Hh*DHh*DHh)/256, 256>>>();
    y_gemm<<<dim3(Tt/128, Bsz*Hh), 256>>>(x, out);
}